// round 8
// baseline (speedup 1.0000x reference)
#include <cuda_runtime.h>

#define WL_L      2048
#define WL_LMASK  2047
#define WL_D      32
#define WL_B      16
#define WL_NT     128                 // 4 warps, one per d-plane

#define WL_G      4                   // d-planes per CTA
#define WL_T      256                 // outputs per plane per CTA
#define WL_HALO   112                 // >= 105 back-reach, multiple of 4
#define WL_EXT    (WL_T + WL_HALO)    // 368 (92 quads)
#define WL_NCHUNK (WL_L / WL_T)       // 8
#define WL_NDG    (WL_D / WL_G)       // 8

typedef unsigned long long u64;

// packed f32x2 ops (Blackwell): lanewise lo and hi fp32 FMA in one instruction
#define FMA2(d, a, b, c) \
    asm("fma.rn.f32x2 %0, %1, %2, %3;" : "=l"(d) : "l"(a), "l"(b), "l"(c))
#define PACK2(d, lo, hi) \
    asm("mov.b64 %0, {%1, %2};" : "=l"(d) : "f"(lo), "f"(hi))
#define UNPACK2(lo, hi, s) \
    asm("mov.b64 {%0, %1}, %2;" : "=f"(lo), "=f"(hi) : "l"(s))

__global__ __launch_bounds__(WL_NT) void wavelet_db4_kernel(
    const float* __restrict__ x,       // (B, L, D)
    const float* __restrict__ w_dec,   // (4, L, L) — only 8 taps read
    const float* __restrict__ v_dec,   // (4, L, L) — only 8 taps read
    float* __restrict__ out)           // (B, D, L, 5)
{
    __shared__ __align__(16) float xs [WL_G][WL_EXT];
    __shared__ __align__(16) float v0s[WL_G][WL_EXT];
    __shared__ __align__(16) float v1s[WL_G][WL_EXT];
    __shared__ __align__(16) float v2s[WL_G][WL_EXT];
    __shared__ float gs[8];
    __shared__ float hs[8];

    const int tid   = threadIdx.x;
    const int blk   = blockIdx.x;
    const int chunk = blk & (WL_NCHUNK - 1);
    const int dg    = (blk >> 3) & (WL_NDG - 1);
    const int b     = blk >> 6;
    const int M0    = chunk * WL_T;
    const int base  = M0 - WL_HALO;

    const int p    = tid >> 5;        // plane 0..3 == warp id
    const int lane = tid & 31;
    const int hq   = lane - 4;        // halo quad id 0..27 on lanes 4..31

    // taps from row 0 of level-0 filters: f[0][0][(0-i) mod L] = tap[i]
    if (tid < 8) {
        int col = (WL_L - tid) & WL_LMASK;
        gs[tid] = v_dec[col];
        hs[tid] = w_dec[col];
    }

    // amortized gather: one float4 across 4 adjacent d per x-row
    {
        const float* xp = x + ((size_t)b * WL_L * WL_D) + dg * WL_G;
        #pragma unroll
        for (int l = tid; l < WL_EXT; l += WL_NT) {
            int gl = (base + l) & WL_LMASK;
            float4 qv = *(const float4*)(xp + (size_t)gl * WL_D);
            xs[0][l] = qv.x; xs[1][l] = qv.y; xs[2][l] = qv.z; xs[3][l] = qv.w;
        }
    }
    __syncthreads();   // the ONLY CTA-wide barrier

    float g[8], h[8];
    u64 gp[8], hp[8];
    #pragma unroll
    for (int i = 0; i < 8; i++) {
        g[i] = gs[i]; h[i] = hs[i];
        PACK2(gp[i], g[i], g[i]);
        PACK2(hp[i], h[i], h[i]);
    }

    const float4*     xs4  = (const float4*)(&xs[p][0]);
    const ulonglong2* v0u  = (const ulonglong2*)(&v0s[p][0]);
    const ulonglong2* v1u  = (const ulonglong2*)(&v1s[p][0]);
    const ulonglong2* v2u  = (const ulonglong2*)(&v2s[p][0]);
    ulonglong2* v0uw = (ulonglong2*)(&v0s[p][0]);
    ulonglong2* v1uw = (ulonglong2*)(&v1s[p][0]);
    ulonglong2* v2uw = (ulonglong2*)(&v2s[p][0]);
    float4*     v0f  = (float4*)(&v0s[p][0]);

    // two output quads per thread: quad indices 28+lane and 60+lane
    int b4s[2]; b4s[0] = 28 + lane; b4s[1] = 60 + lane;

    u64 w0p[2][2], w1p[2][2], w2p[2][2];

    // ── stage 1: dilation 1 on xs → v0 (g) + w0 (h)
    #pragma unroll
    for (int s = 0; s < 2; s++) {
        int b4 = b4s[s];
        int wb = b4 - 2;
        float4 A = xs4[wb], B = xs4[wb + 1], C = xs4[wb + 2];
        float win[12] = {A.x,A.y,A.z,A.w, B.x,B.y,B.z,B.w, C.x,C.y,C.z,C.w};
        u64 P[11];
        #pragma unroll
        for (int k = 1; k <= 10; k++) PACK2(P[k], win[k], win[k + 1]);
        u64 vg01 = 0, vg23 = 0, vh01 = 0, vh23 = 0;
        #pragma unroll
        for (int i = 0; i < 8; i++) {
            FMA2(vg01, gp[i], P[ 8 - i], vg01);
            FMA2(vg23, gp[i], P[10 - i], vg23);
            FMA2(vh01, hp[i], P[ 8 - i], vh01);
            FMA2(vh23, hp[i], P[10 - i], vh23);
        }
        v0uw[b4] = make_ulonglong2(vg01, vg23);
        w0p[s][0] = vh01; w0p[s][1] = vh23;
    }
    if (hq >= 2) {                    // halo v0 (g only, scalar), l0h >= 8
        int wbh = hq - 2;
        float4 A = xs4[wbh], B = xs4[wbh + 1], C = xs4[wbh + 2];
        float hw[12] = {A.x,A.y,A.z,A.w, B.x,B.y,B.z,B.w, C.x,C.y,C.z,C.w};
        float a0=0.f, a1=0.f, a2=0.f, a3=0.f;
        #pragma unroll
        for (int i = 0; i < 8; i++) {
            a0 += g[i] * hw[ 8 - i]; a1 += g[i] * hw[ 9 - i];
            a2 += g[i] * hw[10 - i]; a3 += g[i] * hw[11 - i];
        }
        v0f[hq] = make_float4(a0, a1, a2, a3);
    }
    __syncwarp();

    // ── stage 2: dilation 2 on v0 → v1 (g) + w1 (h); even pairs are natural
    #pragma unroll
    for (int s = 0; s < 2; s++) {
        int b4 = b4s[s];
        int wb = b4 - 4;
        u64 W[10];
        #pragma unroll
        for (int kk = 0; kk < 5; kk++) {
            ulonglong2 t = v0u[wb + kk];
            W[2*kk] = t.x; W[2*kk + 1] = t.y;
        }
        u64 vg01 = 0, vg23 = 0, vh01 = 0, vh23 = 0;
        #pragma unroll
        for (int i = 0; i < 8; i++) {
            FMA2(vg01, gp[i], W[8 - i], vg01);
            FMA2(vg23, gp[i], W[9 - i], vg23);
            FMA2(vh01, hp[i], W[8 - i], vh01);
            FMA2(vh23, hp[i], W[9 - i], vh23);
        }
        v1uw[b4] = make_ulonglong2(vg01, vg23);
        w1p[s][0] = vh01; w1p[s][1] = vh23;
    }
    if (hq >= 7) {                    // halo v1 (g only), l0h >= 28
        int wbh = hq - 4;
        u64 W[10];
        #pragma unroll
        for (int kk = 0; kk < 5; kk++) {
            ulonglong2 t = v0u[wbh + kk];
            W[2*kk] = t.x; W[2*kk + 1] = t.y;
        }
        u64 a01 = 0, a23 = 0;
        #pragma unroll
        for (int i = 0; i < 8; i++) {
            FMA2(a01, gp[i], W[8 - i], a01);
            FMA2(a23, gp[i], W[9 - i], a23);
        }
        v1uw[hq] = make_ulonglong2(a01, a23);
    }
    __syncwarp();

    // ── stage 3: dilation 4 on v1 → v2 (g) + w2 (h); one quad per tap
    #pragma unroll
    for (int s = 0; s < 2; s++) {
        int b4 = b4s[s];
        u64 vg01 = 0, vg23 = 0, vh01 = 0, vh23 = 0;
        #pragma unroll
        for (int i = 0; i < 8; i++) {
            ulonglong2 t = v1u[b4 - i];
            FMA2(vg01, gp[i], t.x, vg01);
            FMA2(vg23, gp[i], t.y, vg23);
            FMA2(vh01, hp[i], t.x, vh01);
            FMA2(vh23, hp[i], t.y, vh23);
        }
        v2uw[b4] = make_ulonglong2(vg01, vg23);
        w2p[s][0] = vh01; w2p[s][1] = vh23;
    }
    if (hq >= 14) {                   // halo v2 (g only), l0h >= 56
        u64 a01 = 0, a23 = 0;
        #pragma unroll
        for (int i = 0; i < 8; i++) {
            ulonglong2 t = v1u[hq - i];
            FMA2(a01, gp[i], t.x, a01);
            FMA2(a23, gp[i], t.y, a23);
        }
        v2uw[hq] = make_ulonglong2(a01, a23);
    }
    __syncwarp();

    // ── stage 4: dilation 8 on v2 → w3 (h) + v3 (g); write all 5 coeffs
    const int bd = b * WL_D + dg * WL_G + p;
    #pragma unroll
    for (int s = 0; s < 2; s++) {
        int b4 = b4s[s];
        u64 w301 = 0, w323 = 0, v301 = 0, v323 = 0;
        #pragma unroll
        for (int i = 0; i < 8; i++) {
            ulonglong2 t = v2u[b4 - 2*i];
            FMA2(w301, hp[i], t.x, w301);
            FMA2(w323, hp[i], t.y, w323);
            FMA2(v301, gp[i], t.x, v301);
            FMA2(v323, gp[i], t.y, v323);
        }

        float w0[4], w1[4], w2[4], w3[4], v3[4];
        UNPACK2(w0[0], w0[1], w0p[s][0]); UNPACK2(w0[2], w0[3], w0p[s][1]);
        UNPACK2(w1[0], w1[1], w1p[s][0]); UNPACK2(w1[2], w1[3], w1p[s][1]);
        UNPACK2(w2[0], w2[1], w2p[s][0]); UNPACK2(w2[2], w2[3], w2p[s][1]);
        UNPACK2(w3[0], w3[1], w301);      UNPACK2(w3[2], w3[3], w323);
        UNPACK2(v3[0], v3[1], v301);      UNPACK2(v3[2], v3[3], v323);

        float o[20];
        #pragma unroll
        for (int j = 0; j < 4; j++) {
            o[j*5 + 0] = w0[j];
            o[j*5 + 1] = w1[j];
            o[j*5 + 2] = w2[j];
            o[j*5 + 3] = w3[j];
            o[j*5 + 4] = v3[j];
        }
        const int m0 = M0 + 4 * (b4 - 28);
        float4* og = (float4*)(out + ((size_t)bd * WL_L + m0) * 5);
        #pragma unroll
        for (int kk = 0; kk < 5; kk++) og[kk] = ((const float4*)o)[kk];
    }
}

extern "C" void kernel_launch(void* const* d_in, const int* in_sizes, int n_in,
                              void* d_out, int out_size) {
    const float* x     = (const float*)d_in[0];
    const float* w_dec = (const float*)d_in[1];
    const float* v_dec = (const float*)d_in[2];
    float* out = (float*)d_out;

    wavelet_db4_kernel<<<WL_B * WL_NDG * WL_NCHUNK, WL_NT>>>(x, w_dec, v_dec, out);
}